// round 17
// baseline (speedup 1.0000x reference)
#include <cuda_runtime.h>
#include <cuda_fp16.h>
#include <mma.h>
#include <math.h>
#include <stdint.h>

using namespace nvcuda;

// Problem constants (fixed shapes)
#define NN 100000
#define EE 1000000
#define F_IN 64
#define EMB 32
#define HH 4
#define CC 32
#define HCC 128
#define NEG_SLOPE 0.2f

// ---------------- scratch (device globals; no allocation allowed) ----------
__device__ __align__(16) __half g_hh[(size_t)NN * HCC];   // fp16 activations
__device__ __align__(16) __half g_xl[(size_t)NN * HCC];
__device__ __align__(16) __half g_xr[(size_t)NN * HCC];
__device__ __align__(16) __half g_sk[(size_t)NN * HCC];
__device__ int   g_deg[NN];
__device__ int   g_rowptr[NN + 1];
__device__ int   g_cursor[NN];
__device__ int   g_csr[EE];
// packed per-layer weights fp16: Wp[K, 384] = Wl | Wr | Ws ; biases fp32 [384]
__device__ __align__(16) __half g_Wf [EMB * 384];
__device__ float g_bf [384];
__device__ __align__(16) __half g_Wm [HCC * 384];
__device__ float g_bm [384];
__device__ __align__(16) __half g_Wl2[HCC * 384];
__device__ float g_bl2[384];

// ---------------- small utility kernels -----------------------------------
__global__ void zero_int_kernel(int* p, int n) {
    int i = blockIdx.x * blockDim.x + threadIdx.x;
    if (i < n) p[i] = 0;
}

__global__ void hist_kernel(const int* __restrict__ dst, int* __restrict__ deg, int e) {
    int i = blockIdx.x * blockDim.x + threadIdx.x;
    if (i < e) atomicAdd(&deg[dst[i]], 1);
}

__global__ void scan_kernel(const int* __restrict__ deg, int* __restrict__ rowptr,
                            int* __restrict__ cursor, int n) {
    __shared__ int sums[1024];
    int tid = threadIdx.x;
    int chunk = (n + 1023) / 1024;
    int start = tid * chunk;
    int end   = min(start + chunk, n);
    int s = 0;
    for (int i = start; i < end; ++i) s += deg[i];
    sums[tid] = s;
    __syncthreads();
    for (int off = 1; off < 1024; off <<= 1) {
        int v = 0;
        if (tid >= off) v = sums[tid - off];
        __syncthreads();
        if (tid >= off) sums[tid] += v;
        __syncthreads();
    }
    int prefix = (tid == 0) ? 0 : sums[tid - 1];
    for (int i = start; i < end; ++i) {
        rowptr[i] = prefix;
        cursor[i] = prefix;
        prefix += deg[i];
    }
    if (tid == 1023) rowptr[n] = sums[1023];
}

__global__ void scatter_kernel(const int* __restrict__ src, const int* __restrict__ dst,
                               int* __restrict__ cursor, int* __restrict__ csr, int e) {
    int i = blockIdx.x * blockDim.x + threadIdx.x;
    if (i < e) {
        int d = dst[i];
        int pos = atomicAdd(&cursor[d], 1);
        csr[pos] = src[i];
    }
}

// pack Wl|Wr|Ws (each [K,128] row-major fp32) -> fp16 Wp [K,384]; biases fp32
__global__ void pack_h_kernel(const float* __restrict__ Wl, const float* __restrict__ Wr,
                              const float* __restrict__ Ws,
                              const float* __restrict__ bl, const float* __restrict__ br,
                              const float* __restrict__ bs,
                              __half* __restrict__ Wp, float* __restrict__ bp, int K) {
    int i = blockIdx.x * blockDim.x + threadIdx.x;
    int total = K * 128;
    if (i < total) {
        int k = i / 128, c = i % 128;
        Wp[(size_t)k * 384 + c]       = __float2half(Wl[i]);
        Wp[(size_t)k * 384 + 128 + c] = __float2half(Wr[i]);
        Wp[(size_t)k * 384 + 256 + c] = __float2half(Ws[i]);
    }
    if (i < 128) {
        bp[i]       = bl[i];
        bp[128 + i] = br[i];
        bp[256 + i] = bs[i];
    }
}

// ---------------- plain SGEMM for x @ W0 -> relu -> fp16 h0 ----------------
#define BM 128
#define BN 32
#define BK 16

__global__ __launch_bounds__(256, 2)
void gemm0_kernel(const float* __restrict__ A, const float* __restrict__ W,
                  __half* __restrict__ C, int M, int K, int Nc) {
    __shared__ float As[BK][BM + 4];
    __shared__ float Bs[BK][BN];

    int bm = blockIdx.x * BM;
    int tid = threadIdx.x;
    int tx = tid & 7;
    int ty = tid >> 3;

    float acc[4][4];
#pragma unroll
    for (int i = 0; i < 4; ++i)
#pragma unroll
        for (int j = 0; j < 4; ++j) acc[i][j] = 0.f;

    for (int k0 = 0; k0 < K; k0 += BK) {
#pragma unroll
        for (int i = tid; i < BM * BK; i += 256) {
            int r = i / BK, c = i % BK;
            int gm = bm + r;
            As[c][r] = (gm < M) ? A[(size_t)gm * K + (k0 + c)] : 0.f;
        }
#pragma unroll
        for (int i = tid; i < BK * BN; i += 256) {
            int r = i / BN, c = i % BN;
            Bs[r][c] = W[(size_t)(k0 + r) * Nc + c];
        }
        __syncthreads();

#pragma unroll
        for (int kk = 0; kk < BK; ++kk) {
            float a[4], b[4];
#pragma unroll
            for (int i = 0; i < 4; ++i) a[i] = As[kk][ty * 4 + i];
#pragma unroll
            for (int j = 0; j < 4; ++j) b[j] = Bs[kk][tx * 4 + j];
#pragma unroll
            for (int i = 0; i < 4; ++i)
#pragma unroll
                for (int j = 0; j < 4; ++j) acc[i][j] += a[i] * b[j];
        }
        __syncthreads();
    }

#pragma unroll
    for (int i = 0; i < 4; ++i) {
        int gm = bm + ty * 4 + i;
        if (gm >= M) continue;
        __half2 w0 = __floats2half2_rn(fmaxf(acc[i][0], 0.f), fmaxf(acc[i][1], 0.f));
        __half2 w1 = __floats2half2_rn(fmaxf(acc[i][2], 0.f), fmaxf(acc[i][3], 0.f));
        uint2 u;
        u.x = *reinterpret_cast<uint32_t*>(&w0);
        u.y = *reinterpret_cast<uint32_t*>(&w1);
        *reinterpret_cast<uint2*>(C + (size_t)gm * Nc + tx * 4) = u;
    }
}

// ---------------- fused fp16 wmma GEMM: A staged once, 3 outputs -----------
#define A_LDF 136
#define B_LDF 136
#define SM_AS   0
#define SM_BS   34816
#define SM_STG  69632
#define SM_TOTAL (69632 + 10240)

__global__ __launch_bounds__(256, 2)
void gemm_h16_fused(const __half* __restrict__ A, const __half* __restrict__ B,
                    const float* __restrict__ bias,
                    __half* __restrict__ xl, __half* __restrict__ xr,
                    __half* __restrict__ sk, int M, int K) {
    extern __shared__ __align__(16) char dynbuf[];
    __half* As = reinterpret_cast<__half*>(dynbuf + SM_AS);
    __half* Bs = reinterpret_cast<__half*>(dynbuf + SM_BS);
    float*  stg = reinterpret_cast<float*>(dynbuf + SM_STG);

    const int tid = threadIdx.x;
    const int warp = tid >> 5;
    const int lane = tid & 31;
    const int wm = warp >> 1;
    const int wn = warp & 1;
    const int bm = blockIdx.x * 128;

    const int kv = K >> 3;
    for (int i = tid; i < 128 * kv; i += 256) {
        int r = i / kv, c = (i % kv) * 8;
        int gm = bm + r;
        uint4 v = make_uint4(0, 0, 0, 0);
        if (gm < M) v = *reinterpret_cast<const uint4*>(A + (size_t)gm * K + c);
        *reinterpret_cast<uint4*>(&As[r * A_LDF + c]) = v;
    }
    __syncthreads();

    float* stage = stg + warp * 320;

    for (int sel = 0; sel < 3; ++sel) {
        for (int i = tid; i < K * 16; i += 256) {
            int r = i >> 4, c = (i & 15) * 8;
            uint4 v = *reinterpret_cast<const uint4*>(B + (size_t)r * 384 + sel * 128 + c);
            *reinterpret_cast<uint4*>(&Bs[r * B_LDF + c]) = v;
        }
        __syncthreads();

        wmma::fragment<wmma::accumulator, 16, 16, 16, float> fc[2][4];
#pragma unroll
        for (int i = 0; i < 2; ++i)
#pragma unroll
            for (int j = 0; j < 4; ++j) wmma::fill_fragment(fc[i][j], 0.f);

        for (int kk = 0; kk < K; kk += 16) {
            wmma::fragment<wmma::matrix_a, 16, 16, 16, __half, wmma::row_major> fa[2];
            wmma::fragment<wmma::matrix_b, 16, 16, 16, __half, wmma::row_major> fb[4];
#pragma unroll
            for (int i = 0; i < 2; ++i)
                wmma::load_matrix_sync(fa[i], &As[(wm * 32 + i * 16) * A_LDF + kk], A_LDF);
#pragma unroll
            for (int j = 0; j < 4; ++j)
                wmma::load_matrix_sync(fb[j], &Bs[kk * B_LDF + wn * 64 + j * 16], B_LDF);
#pragma unroll
            for (int i = 0; i < 2; ++i)
#pragma unroll
                for (int j = 0; j < 4; ++j)
                    wmma::mma_sync(fc[i][j], fa[i], fb[j], fc[i][j]);
        }

        __half* outp = (sel == 0) ? xl : ((sel == 1) ? xr : sk);

        const int lr = lane >> 1;
        const int lc = (lane & 1) * 8;
#pragma unroll
        for (int i = 0; i < 2; ++i) {
#pragma unroll
            for (int j = 0; j < 4; ++j) {
                wmma::store_matrix_sync(stage, fc[i][j], 20, wmma::mem_row_major);
                __syncwarp();
                int gm = bm + wm * 32 + i * 16 + lr;
                int c0 = wn * 64 + j * 16 + lc;
                if (gm < M) {
                    const float* sp = stage + lr * 20 + lc;
                    float4 v0 = *reinterpret_cast<const float4*>(sp);
                    float4 v1 = *reinterpret_cast<const float4*>(sp + 4);
                    float4 b0 = *reinterpret_cast<const float4*>(bias + sel * 128 + c0);
                    float4 b1 = *reinterpret_cast<const float4*>(bias + sel * 128 + c0 + 4);
                    __half2 h0 = __floats2half2_rn(v0.x + b0.x, v0.y + b0.y);
                    __half2 h1 = __floats2half2_rn(v0.z + b0.z, v0.w + b0.w);
                    __half2 h2 = __floats2half2_rn(v1.x + b1.x, v1.y + b1.y);
                    __half2 h3 = __floats2half2_rn(v1.z + b1.z, v1.w + b1.w);
                    uint4 u;
                    u.x = *reinterpret_cast<uint32_t*>(&h0);
                    u.y = *reinterpret_cast<uint32_t*>(&h1);
                    u.z = *reinterpret_cast<uint32_t*>(&h2);
                    u.w = *reinterpret_cast<uint32_t*>(&h3);
                    *reinterpret_cast<uint4*>(outp + (size_t)gm * HCC + c0) = u;
                }
                __syncwarp();
            }
        }
        __syncthreads();
    }
}

// ---------------- GAT edge kernel: warp per node, 8 lanes per head ---------
// 4-edge batched online softmax; prefetch 4 ahead (8 gathers in flight/lane).
__global__ __launch_bounds__(256)
void gat_edge_kernel(const int* __restrict__ rowptr, const int* __restrict__ csr,
                     const __half* __restrict__ xl, const __half* __restrict__ xr,
                     const __half* __restrict__ sk,
                     const float* __restrict__ att, const float* __restrict__ cb,
                     __half* __restrict__ outh, float* __restrict__ outf, int n) {
    int warp_id = (blockIdx.x * blockDim.x + threadIdx.x) >> 5;
    if (warp_id >= n) return;
    const int lane = threadIdx.x & 31;
    const int node = warp_id;
    const int head = lane >> 3;
    const int chan = head * CC + (lane & 7) * 4;

    float xrv[4], attv[4];
    {
        uint2 u = *reinterpret_cast<const uint2*>(xr + (size_t)node * HCC + chan);
        __half2 h0 = *reinterpret_cast<__half2*>(&u.x);
        __half2 h1 = *reinterpret_cast<__half2*>(&u.y);
        xrv[0] = __low2float(h0); xrv[1] = __high2float(h0);
        xrv[2] = __low2float(h1); xrv[3] = __high2float(h1);
        float4 a = *reinterpret_cast<const float4*>(att + chan);
        attv[0] = a.x; attv[1] = a.y; attv[2] = a.z; attv[3] = a.w;
    }

    float m = -INFINITY, den = 0.f;
    float acc[4] = {0.f, 0.f, 0.f, 0.f};

    const int e0 = rowptr[node], e1 = rowptr[node + 1];
    int rem = e1 - e0;
    int e = e0;
    uint2 u[4];
#pragma unroll
    for (int i = 0; i < 4; ++i) u[i] = make_uint2(0, 0);
#pragma unroll
    for (int i = 0; i < 4; ++i) {
        if (i < rem) {
            int s = __ldg(&csr[e + i]);
            u[i] = *reinterpret_cast<const uint2*>(xl + (size_t)s * HCC + chan);
        }
    }

    while (rem >= 4) {
        uint2 c0 = u[0], c1 = u[1], c2 = u[2], c3 = u[3];
        int nxt = rem - 4;
#pragma unroll
        for (int i = 0; i < 4; ++i) {
            if (i < nxt) {
                int s = __ldg(&csr[e + 4 + i]);
                u[i] = *reinterpret_cast<const uint2*>(xl + (size_t)s * HCC + chan);
            }
        }
        float xla[4][4];
        {
            uint2 cc[4] = {c0, c1, c2, c3};
#pragma unroll
            for (int q = 0; q < 4; ++q) {
                __half2 h0 = *reinterpret_cast<__half2*>(&cc[q].x);
                __half2 h1 = *reinterpret_cast<__half2*>(&cc[q].y);
                xla[q][0] = __low2float(h0); xla[q][1] = __high2float(h0);
                xla[q][2] = __low2float(h1); xla[q][3] = __high2float(h1);
            }
        }
        float s4[4] = {0.f, 0.f, 0.f, 0.f};
#pragma unroll
        for (int q = 0; q < 4; ++q) {
#pragma unroll
            for (int j = 0; j < 4; ++j) {
                float t = xla[q][j] + xrv[j];
                t = (t > 0.f) ? t : NEG_SLOPE * t;
                s4[q] = fmaf(t, attv[j], s4[q]);
            }
        }
#pragma unroll
        for (int off = 4; off > 0; off >>= 1) {
#pragma unroll
            for (int q = 0; q < 4; ++q)
                s4[q] += __shfl_xor_sync(0xffffffffu, s4[q], off);
        }
        // batched online-softmax update over 4 edges (exact)
        float nm = fmaxf(fmaxf(m, s4[0]), fmaxf(fmaxf(s4[1], s4[2]), s4[3]));
        float scale = __expf(m - nm);
        float p0 = __expf(s4[0] - nm);
        float p1 = __expf(s4[1] - nm);
        float p2 = __expf(s4[2] - nm);
        float p3 = __expf(s4[3] - nm);
        den = den * scale + p0 + p1 + p2 + p3;
#pragma unroll
        for (int j = 0; j < 4; ++j) {
            float add = fmaf(p0, xla[0][j],
                        fmaf(p1, xla[1][j],
                        fmaf(p2, xla[2][j], p3 * xla[3][j])));
            acc[j] = fmaf(acc[j], scale, add);
        }
        m = nm;
        e += 4; rem -= 4;
    }

    // tail: rem in 0..3, data already in u[0..rem-1]
#pragma unroll
    for (int q = 0; q < 3; ++q) {
        if (q < rem) {
            __half2 h0 = *reinterpret_cast<__half2*>(&u[q].x);
            __half2 h1 = *reinterpret_cast<__half2*>(&u[q].y);
            float xla[4] = {__low2float(h0), __high2float(h0),
                            __low2float(h1), __high2float(h1)};
            float sa = 0.f;
#pragma unroll
            for (int j = 0; j < 4; ++j) {
                float t = xla[j] + xrv[j];
                t = (t > 0.f) ? t : NEG_SLOPE * t;
                sa = fmaf(t, attv[j], sa);
            }
            sa += __shfl_xor_sync(0xffffffffu, sa, 4);
            sa += __shfl_xor_sync(0xffffffffu, sa, 2);
            sa += __shfl_xor_sync(0xffffffffu, sa, 1);
            float nm = fmaxf(m, sa);
            float scale = __expf(m - nm);
            float p = __expf(sa - nm);
            den = den * scale + p;
#pragma unroll
            for (int j = 0; j < 4; ++j)
                acc[j] = fmaf(acc[j], scale, p * xla[j]);
            m = nm;
        }
    }

    float inv_den = (den > 0.f) ? (1.f / den) : 0.f;
    float o[4];
    {
        uint2 us = *reinterpret_cast<const uint2*>(sk + (size_t)node * HCC + chan);
        __half2 h0 = *reinterpret_cast<__half2*>(&us.x);
        __half2 h1 = *reinterpret_cast<__half2*>(&us.y);
        float skv[4] = {__low2float(h0), __high2float(h0),
                        __low2float(h1), __high2float(h1)};
        float4 c = *reinterpret_cast<const float4*>(cb + chan);
        o[0] = acc[0] * inv_den + c.x + skv[0];
        o[1] = acc[1] * inv_den + c.y + skv[1];
        o[2] = acc[2] * inv_den + c.z + skv[2];
        o[3] = acc[3] * inv_den + c.w + skv[3];
    }

    if (outh) {
        __half2 w0 = __floats2half2_rn(fmaxf(o[0], 0.f), fmaxf(o[1], 0.f));
        __half2 w1 = __floats2half2_rn(fmaxf(o[2], 0.f), fmaxf(o[3], 0.f));
        uint2 uo;
        uo.x = *reinterpret_cast<uint32_t*>(&w0);
        uo.y = *reinterpret_cast<uint32_t*>(&w1);
        *reinterpret_cast<uint2*>(outh + (size_t)node * HCC + chan) = uo;
    } else {
        float sq = o[0] * o[0] + o[1] * o[1] + o[2] * o[2] + o[3] * o[3];
#pragma unroll
        for (int off = 16; off > 0; off >>= 1)
            sq += __shfl_xor_sync(0xffffffffu, sq, off);
        float inv = rsqrtf(sq);
        float4 w = make_float4(o[0] * inv, o[1] * inv, o[2] * inv, o[3] * inv);
        *reinterpret_cast<float4*>(outf + (size_t)node * HCC + chan) = w;
    }
}

// ---------------- host ------------------------------------------------------
extern "C" void kernel_launch(void* const* d_in, const int* in_sizes, int n_in,
                              void* d_out, int out_size) {
    const float* x  = (const float*)d_in[0];
    const int*   ei = (const int*)d_in[1];
    const float* W0 = (const float*)d_in[2];

    const float* P[27];
    for (int i = 3; i < 27; ++i) P[i] = (const float*)d_in[i];

    __half *hh, *xl, *xr, *sk, *Wf, *Wm, *Wl2;
    float *bf, *bm_, *bl2;
    int *deg, *rowptr, *cursor, *csr;
    cudaGetSymbolAddress((void**)&hh,     g_hh);
    cudaGetSymbolAddress((void**)&xl,     g_xl);
    cudaGetSymbolAddress((void**)&xr,     g_xr);
    cudaGetSymbolAddress((void**)&sk,     g_sk);
    cudaGetSymbolAddress((void**)&deg,    g_deg);
    cudaGetSymbolAddress((void**)&rowptr, g_rowptr);
    cudaGetSymbolAddress((void**)&cursor, g_cursor);
    cudaGetSymbolAddress((void**)&csr,    g_csr);
    cudaGetSymbolAddress((void**)&Wf,     g_Wf);
    cudaGetSymbolAddress((void**)&bf,     g_bf);
    cudaGetSymbolAddress((void**)&Wm,     g_Wm);
    cudaGetSymbolAddress((void**)&bm_,    g_bm);
    cudaGetSymbolAddress((void**)&Wl2,    g_Wl2);
    cudaGetSymbolAddress((void**)&bl2,    g_bl2);

    cudaFuncSetAttribute(gemm_h16_fused,
                         cudaFuncAttributeMaxDynamicSharedMemorySize, SM_TOTAL);

    const int* src = ei;
    const int* dst = ei + EE;

    // ---- CSR build (by dst) ----
    zero_int_kernel<<<(NN + 255) / 256, 256>>>(deg, NN);
    hist_kernel<<<(EE + 255) / 256, 256>>>(dst, deg, EE);
    scan_kernel<<<1, 1024>>>(deg, rowptr, cursor, NN);
    scatter_kernel<<<(EE + 255) / 256, 256>>>(src, dst, cursor, csr, EE);

    // ---- pack per-layer weights to fp16 ----
    pack_h_kernel<<<(EMB * 128 + 255) / 256, 256>>>(P[3], P[5], P[9], P[4], P[6], P[10], Wf, bf, EMB);
    pack_h_kernel<<<(HCC * 128 + 255) / 256, 256>>>(P[11], P[13], P[17], P[12], P[14], P[18], Wm, bm_, HCC);
    pack_h_kernel<<<(HCC * 128 + 255) / 256, 256>>>(P[19], P[21], P[25], P[20], P[22], P[26], Wl2, bl2, HCC);

    // h0 = relu(x @ W0)  [N, 32] fp16
    gemm0_kernel<<<(NN + BM - 1) / BM, 256>>>(x, W0, hh, NN, F_IN, EMB);

    int gemm_blocks = (NN + 127) / 128;
    int edge_blocks = (NN * 32 + 255) / 256;

    auto run_layer = [&](const __half* Wp, const float* bp, int K,
                         const float* att, const float* cb,
                         __half* outh, float* outf) {
        gemm_h16_fused<<<gemm_blocks, 256, SM_TOTAL>>>(hh, Wp, bp, xl, xr, sk, NN, K);
        gat_edge_kernel<<<edge_blocks, 256>>>(rowptr, csr, xl, xr, sk, att, cb,
                                              outh, outf, NN);
    };

    run_layer(Wf,  bf,  EMB, P[7],  P[8],  hh, nullptr);   // first GAT layer (K=32)
    run_layer(Wm,  bm_, HCC, P[15], P[16], hh, nullptr);   // mid x3 (shared weights)
    run_layer(Wm,  bm_, HCC, P[15], P[16], hh, nullptr);
    run_layer(Wm,  bm_, HCC, P[15], P[16], hh, nullptr);
    run_layer(Wl2, bl2, HCC, P[23], P[24], nullptr, (float*)d_out);  // last + L2 norm
}